// round 12
// baseline (speedup 1.0000x reference)
#include <cuda_runtime.h>
#include <math_constants.h>

// ChamferDistance: x1,x2 = [B=8, N=M=8192, 3] fp32.
// out = [ loss (1) | dist1 (B*N) | dist2 (B*M) ]
//
// R11: per-WARP x-binned pruned NN with the R6 packed-f32x2 engine.
//  binning: zero/hist/prefix/scatter into bin-grouped float4{x,y,z,idx}.
//  nn: 256 CTAs x 128 thr; each warp independent: 128 contiguous A pts
//      (PTS=4/lane, coords duplicated in f32x2 halves), private 2KB smem
//      strip, __syncwarp only. Seed scan bins [wlo-S, whi+S]; warp-max
//      bound R (+fp margin); residual bins scanned same way. Exact NN =>
//      deterministic; each A stored once (no atomics, no sentinel fill).

constexpr int Bc = 8;
constexpr int Nc = 8192;
constexpr int NBINS = 256;
constexpr float XLO = -4.5f;
constexpr float INV_H = NBINS / 9.0f;         // bins over [-4.5, 4.5]
constexpr int NCB = 16;                       // cloud(2) * batch(8)
constexpr int SEED = 3;                       // seed half-width in bins (~0.105)
constexpr int PTS = 4;                        // A-points per lane
constexpr int WARP_A = 32 * PTS;              // 128 A-points per warp
constexpr int NN_THREADS = 128;               // 4 warps
constexpr int CHUNK_A = 4 * WARP_A;           // 512 A per CTA
constexpr int NN_GRID = NCB * (Nc / CHUNK_A); // 256
constexpr int TB = 128;                       // B-points per tile round
constexpr int TJP = TB / 2;                   // 64 j-pairs

__device__ float4 g_scat[NCB][Nc];            // bin-grouped points
__device__ int g_cnt[NCB][NBINS];
__device__ int g_start[NCB][NBINS + 1];
__device__ int g_cur[NCB][NBINS];
__device__ float g_partials[128];

__device__ __forceinline__ unsigned long long pk2(float lo, float hi) {
    unsigned long long r;
    asm("mov.b64 %0, {%1, %2};" : "=l"(r) : "f"(lo), "f"(hi));
    return r;
}
__device__ __forceinline__ unsigned long long ffma2(unsigned long long a,
                                                    unsigned long long b,
                                                    unsigned long long c) {
    unsigned long long d;
    asm("fma.rn.f32x2 %0, %1, %2, %3;" : "=l"(d) : "l"(a), "l"(b), "l"(c));
    return d;
}
__device__ __forceinline__ void upk2(unsigned long long v, float& lo, float& hi) {
    asm("mov.b64 {%0, %1}, %2;" : "=f"(lo), "=f"(hi) : "l"(v));
}

__device__ __forceinline__ int bin_of(float x) {
    float v = (x - XLO) * INV_H;
    v = fminf(fmaxf(v, 0.0f), 255.0f);        // +-inf safe
    return (int)v;
}

// ---------------- binning kernels ----------------

__global__ void __launch_bounds__(512) zero_kernel() {
    int* p = &g_cnt[0][0];
#pragma unroll
    for (int k = 0; k < 8; k++) p[k * 512 + threadIdx.x] = 0;
}

__global__ void __launch_bounds__(512)
hist_kernel(const float* __restrict__ x1, const float* __restrict__ x2) {
    const int gid = blockIdx.x * 512 + threadIdx.x;      // [0, 131072)
    const int c = gid >> 16;
    const int r = gid & 65535;
    const int b = r >> 13;
    const int i = r & 8191;
    const float* src = c ? x2 : x1;
    const float x = src[((size_t)b * Nc + i) * 3];
    atomicAdd(&g_cnt[c * 8 + b][bin_of(x)], 1);
}

__global__ void __launch_bounds__(512) prefix_kernel() {
    const int cb = threadIdx.x >> 5;           // 16 warps, one per (cloud,batch)
    const int lane = threadIdx.x & 31;
    int cnt[8];
    int s = 0;
#pragma unroll
    for (int k = 0; k < 8; k++) { cnt[k] = g_cnt[cb][lane * 8 + k]; s += cnt[k]; }
    int run = s;
#pragma unroll
    for (int d = 1; d < 32; d <<= 1) {
        int v = __shfl_up_sync(0xffffffffu, run, d);
        if (lane >= d) run += v;
    }
    int excl = run - s;
#pragma unroll
    for (int k = 0; k < 8; k++) {
        g_start[cb][lane * 8 + k] = excl;
        g_cur[cb][lane * 8 + k] = excl;
        excl += cnt[k];
    }
    if (lane == 31) g_start[cb][NBINS] = excl;
}

__global__ void __launch_bounds__(512)
scatter_kernel(const float* __restrict__ x1, const float* __restrict__ x2) {
    const int gid = blockIdx.x * 512 + threadIdx.x;
    const int c = gid >> 16;
    const int r = gid & 65535;
    const int b = r >> 13;
    const int i = r & 8191;
    const float* src = c ? x2 : x1;
    const float* p = src + ((size_t)b * Nc + i) * 3;
    const float x = p[0], y = p[1], z = p[2];
    const int cb = c * 8 + b;
    const int pos = atomicAdd(&g_cur[cb][bin_of(x)], 1);
    g_scat[cb][pos] = make_float4(x, y, z, __int_as_float(i));
}

// ---------------- NN kernel (per-warp) ----------------

// Scan scat positions [lo, hi) against this lane's 4 packed A points using a
// per-warp smem tile. lo/hi warp-uniform. Engine = R6 inner loop.
__device__ __forceinline__ void warp_scan(
    int lo, int hi, const float4* __restrict__ scat, float* wt, int lane,
    const unsigned long long* axp, const unsigned long long* ayp,
    const unsigned long long* azp, float* eminE, float* eminO)
{
    for (int base = lo; base < hi; base += TB) {
        __syncwarp();                          // protect previous tile reads
        // fill: each lane 4 B-points = 2 j-pairs
        float4 q[4];
        const int i0 = base + 4 * lane;
#pragma unroll
        for (int i = 0; i < 4; i++) {
            if (i0 + i < hi) q[i] = scat[i0 + i];
            else q[i] = make_float4(0.0f, 0.0f, 0.0f, 0.0f);
        }
        float n2[4];
#pragma unroll
        for (int i = 0; i < 4; i++) {
            n2[i] = (i0 + i < hi)
                  ? fmaf(q[i].x, q[i].x, fmaf(q[i].y, q[i].y, q[i].z * q[i].z))
                  : 1e30f;                     // sentinel: never the min
        }
        float4* s = reinterpret_cast<float4*>(&wt[(2 * lane) * 8]);
        s[0] = make_float4(-2.0f * q[0].x, -2.0f * q[1].x, -2.0f * q[0].y, -2.0f * q[1].y);
        s[1] = make_float4(-2.0f * q[0].z, -2.0f * q[1].z, n2[0], n2[1]);
        s[2] = make_float4(-2.0f * q[2].x, -2.0f * q[3].x, -2.0f * q[2].y, -2.0f * q[3].y);
        s[3] = make_float4(-2.0f * q[2].z, -2.0f * q[3].z, n2[2], n2[3]);
        __syncwarp();

        const ulonglong2* sp = reinterpret_cast<const ulonglong2*>(wt);
#pragma unroll 8
        for (int jj = 0; jj < TJP; jj++) {
            const ulonglong2 c0 = sp[2 * jj];       // {bx2e,bx2o}{by2e,by2o}
            const ulonglong2 c1 = sp[2 * jj + 1];   // {bz2e,bz2o}{n2e,n2o}
#pragma unroll
            for (int k = 0; k < PTS; k++) {
                unsigned long long e = ffma2(axp[k], c0.x, c1.y);
                e = ffma2(ayp[k], c0.y, e);
                e = ffma2(azp[k], c1.x, e);
                float flo, fhi;
                upk2(e, flo, fhi);
                eminE[k] = fminf(eminE[k], flo);
                eminO[k] = fminf(eminO[k], fhi);
            }
        }
    }
}

__global__ void __launch_bounds__(NN_THREADS)
nn_kernel(float* __restrict__ dist1, float* __restrict__ dist2)
{
    __shared__ __align__(16) float tile[4][TJP * 8];   // 2KB per warp

    const int lane = threadIdx.x & 31;
    const int w = threadIdx.x >> 5;
    const int cbA = blockIdx.x >> 4;          // 16 CTAs per (cloud,batch)
    const int chunk = blockIdx.x & 15;
    const int cbB = cbA ^ 8;
    const int dir = cbA >> 3;                 // 0: A=x1, 1: A=x2
    const int b = cbA & 7;

    // load this lane's 4 contiguous A points
    const int abase = chunk * CHUNK_A + w * WARP_A + lane * PTS;
    unsigned long long axp[PTS], ayp[PTS], azp[PTS];
    float n1s[PTS];
    int oi[PTS];
    float my_amin = CUDART_INF_F, my_amax = -CUDART_INF_F;
#pragma unroll
    for (int k = 0; k < PTS; k++) {
        const float4 A = g_scat[cbA][abase + k];
        axp[k] = pk2(A.x, A.x);
        ayp[k] = pk2(A.y, A.y);
        azp[k] = pk2(A.z, A.z);
        n1s[k] = fmaf(A.x, A.x, fmaf(A.y, A.y, A.z * A.z));
        oi[k] = __float_as_int(A.w);
        my_amin = fminf(my_amin, A.x);
        my_amax = fmaxf(my_amax, A.x);
    }
    // warp x-range
#pragma unroll
    for (int d = 16; d > 0; d >>= 1) {
        my_amin = fminf(my_amin, __shfl_xor_sync(0xffffffffu, my_amin, d));
        my_amax = fmaxf(my_amax, __shfl_xor_sync(0xffffffffu, my_amax, d));
    }
    const float amin = my_amin, amax = my_amax;

    float eminE[PTS], eminO[PTS];
#pragma unroll
    for (int k = 0; k < PTS; k++) { eminE[k] = CUDART_INF_F; eminO[k] = CUDART_INF_F; }

    const float4* scatB = g_scat[cbB];
    float* wt = tile[w];

    // seed scan
    const int slo = max(bin_of(amin) - SEED, 0);
    const int shi = min(bin_of(amax) + SEED, NBINS - 1);
    warp_scan(g_start[cbB][slo], g_start[cbB][shi + 1], scatB, wt, lane,
              axp, ayp, azp, eminE, eminO);

    // warp bound R (+fp safety margin)
    float u = 0.0f;
#pragma unroll
    for (int k = 0; k < PTS; k++)
        u = fmaxf(u, n1s[k] + fminf(eminE[k], eminO[k]));
#pragma unroll
    for (int d = 16; d > 0; d >>= 1)
        u = fmaxf(u, __shfl_xor_sync(0xffffffffu, u, d));
    const float R = sqrtf(fmaxf(u, 0.0f)) * 1.0005f + 1e-3f;

    // residual scans
    const int flo = bin_of(amin - R);
    const int fhi = bin_of(amax + R);
    if (flo < slo)
        warp_scan(g_start[cbB][flo], g_start[cbB][slo], scatB, wt, lane,
                  axp, ayp, azp, eminE, eminO);
    if (fhi > shi)
        warp_scan(g_start[cbB][shi + 1], g_start[cbB][fhi + 1], scatB, wt, lane,
                  axp, ayp, azp, eminE, eminO);

    // store (each A owned by exactly one lane)
    float* __restrict__ outd = dir ? dist2 : dist1;
#pragma unroll
    for (int k = 0; k < PTS; k++) {
        const float d = fmaxf(n1s[k] + fminf(eminE[k], eminO[k]), 0.0f);
        outd[(size_t)b * Nc + oi[k]] = d;
    }
}

// ---------------- deterministic 2-stage loss reduction ----------------

__global__ void __launch_bounds__(256)
sum_stage1(const float* __restrict__ dists)   // dists = out+1, length 2*B*N
{
    __shared__ float red[256];
    const int tid = threadIdx.x;
    const int base = blockIdx.x * 1024;
    float s = 0.0f;
#pragma unroll
    for (int i = 0; i < 4; i++) s += dists[base + i * 256 + tid];
    red[tid] = s;
    __syncthreads();
    for (int w = 128; w > 0; w >>= 1) {
        if (tid < w) red[tid] += red[tid + w];
        __syncthreads();
    }
    if (tid == 0) g_partials[blockIdx.x] = red[0];
}

__global__ void __launch_bounds__(128)
sum_stage2(float* __restrict__ out)
{
    __shared__ float red[128];
    const int tid = threadIdx.x;
    red[tid] = g_partials[tid];
    __syncthreads();
    for (int w = 64; w > 0; w >>= 1) {
        if (tid < w) red[tid] += red[tid + w];
        __syncthreads();
    }
    if (tid == 0) out[0] = red[0] * (1.0f / (float)(Bc * Nc));
}

extern "C" void kernel_launch(void* const* d_in, const int* in_sizes, int n_in,
                              void* d_out, int out_size)
{
    const float* x1 = (const float*)d_in[0];
    const float* x2 = (const float*)d_in[1];
    float* out = (float*)d_out;
    float* dist1 = out + 1;
    float* dist2 = out + 1 + Bc * Nc;

    zero_kernel<<<1, 512>>>();
    hist_kernel<<<256, 512>>>(x1, x2);
    prefix_kernel<<<1, 512>>>();
    scatter_kernel<<<256, 512>>>(x1, x2);
    nn_kernel<<<NN_GRID, NN_THREADS>>>(dist1, dist2);

    sum_stage1<<<128, 256>>>(out + 1);
    sum_stage2<<<1, 128>>>(out);
}

// round 14
// speedup vs baseline: 1.3916x; 1.3916x over previous
#include <cuda_runtime.h>
#include <math_constants.h>
#include <cstdint>

// ChamferDistance: x1,x2 = [B=8, N=M=8192, 3] fp32.
// out = [ loss (1) | dist1 (B*N) | dist2 (B*M) ]
//
// R14 = R13 with the missing <cstdint> include. R6 dense engine (PTS=4 packed
// f32x2, 512 thr, 2 CTAs/SM, 2048 balanced tiles, atomicMin combine, 0x7F
// sentinel) with B tiles PREPPED into packed-dup format in global by a
// one-time kernel, and the per-round fill done via cp.async.cg (LDGSTS)
// fully overlapped with compute.

constexpr int Bc = 8;
constexpr int Nc = 8192;
constexpr int Mc = 8192;
constexpr int THREADS = 512;
constexpr int PTS = 4;                        // A-points per thread (each dup'd)
constexpr int TILE_N = THREADS * PTS;         // 2048
constexpr int NCHUNKS = Nc / TILE_N;          // 4
constexpr int TILE_M = 256;                   // B-points per slice
constexpr int JP = TILE_M / 2;                // 128 j-pairs, tile = 4 KB
constexpr int MSLICES = Mc / TILE_M;          // 32
constexpr int NACH = 2 * Bc * NCHUNKS;        // 64 A-chunks
constexpr int NTILES = NACH * MSLICES;        // 2048
constexpr int GRID = 296;                     // 2 CTAs per SM

// prepped B: [cloud][batch][jp*8 floats]  (jp-pair packed-dup layout, 2 MB)
__device__ float g_prepB[2][Bc][(Mc / 2) * 8];
__device__ float g_partials[128];

__device__ __forceinline__ unsigned long long pk2(float lo, float hi) {
    unsigned long long r;
    asm("mov.b64 %0, {%1, %2};" : "=l"(r) : "f"(lo), "f"(hi));
    return r;
}
__device__ __forceinline__ unsigned long long ffma2(unsigned long long a,
                                                    unsigned long long b,
                                                    unsigned long long c) {
    unsigned long long d;
    asm("fma.rn.f32x2 %0, %1, %2, %3;" : "=l"(d) : "l"(a), "l"(b), "l"(c));
    return d;
}
__device__ __forceinline__ void upk2(unsigned long long v, float& lo, float& hi) {
    asm("mov.b64 {%0, %1}, %2;" : "=f"(lo), "=f"(hi) : "l"(v));
}
__device__ __forceinline__ void cp_async16(uint32_t smem_dst, const void* gsrc) {
    asm volatile("cp.async.cg.shared.global [%0], [%1], 16;"
                 :: "r"(smem_dst), "l"(gsrc) : "memory");
}
__device__ __forceinline__ void cp_commit() {
    asm volatile("cp.async.commit_group;" ::: "memory");
}
__device__ __forceinline__ void cp_wait0() {
    asm volatile("cp.async.wait_group 0;" ::: "memory");
}

// decode tile id -> (dir, b, nbase, ms)
__device__ __forceinline__ void decode_tile(int t, int& dir, int& b, int& nbase, int& ms) {
    const int ach = t >> 5;          // [0,64)
    ms = t & (MSLICES - 1);
    const int db = ach >> 2;         // dir*8 + b
    dir = db >> 3;
    b = db & 7;
    nbase = (ach & 3) * TILE_N;
}

// ---------------- prep kernel: pack B clouds into tile format ----------------
__global__ void __launch_bounds__(256)
prep_kernel(const float* __restrict__ x1, const float* __restrict__ x2)
{
    const int gid = blockIdx.x * 256 + threadIdx.x;   // [0, 65536)
    const int c = gid >> 15;                          // cloud
    const int r = gid & 32767;
    const int b = r >> 12;                            // batch
    const int jp = r & 4095;                          // j-pair
    const float* src = (c ? x2 : x1) + ((size_t)b * Mc + 2 * jp) * 3;
    const float bxe = src[0], bye = src[1], bze = src[2];
    const float bxo = src[3], byo = src[4], bzo = src[5];
    const float n2e = fmaf(bxe, bxe, fmaf(bye, bye, bze * bze));
    const float n2o = fmaf(bxo, bxo, fmaf(byo, byo, bzo * bzo));
    float4* d = reinterpret_cast<float4*>(&g_prepB[c][b][(size_t)jp * 8]);
    d[0] = make_float4(-2.0f * bxe, -2.0f * bxo, -2.0f * bye, -2.0f * byo);
    d[1] = make_float4(-2.0f * bze, -2.0f * bzo, n2e, n2o);
}

// ---------------- main kernel ----------------
__global__ void __launch_bounds__(THREADS, 2)
chamfer_pass_kernel(const float* __restrict__ x1, const float* __restrict__ x2,
                    float* __restrict__ dist1, float* __restrict__ dist2)
{
    // 2 buffers, 4 KB each, filled by cp.async from g_prepB
    __shared__ __align__(16) float tile[2][JP * 8];

    const int tid = threadIdx.x;
    const int bid = blockIdx.x;
    const int tstart = (bid * NTILES) / GRID;
    const int tend   = ((bid + 1) * NTILES) / GRID;

    unsigned long long axp[PTS], ayp[PTS], azp[PTS];
    float n1s[PTS];
    float eminE[PTS], eminO[PTS];
    int cur_ach = -1;
    int cur_dir = 0, cur_b = 0, cur_nbase = 0;

    // prologue: async-fill buffer 0 with tile tstart
    {
        int dir, b, nbase, ms;
        decode_tile(tstart, dir, b, nbase, ms);
        if (tid < 256) {
            const float* gsrc = &g_prepB[dir ^ 1][b][(size_t)ms * JP * 8] + tid * 4;
            const uint32_t dst = (uint32_t)__cvta_generic_to_shared(&tile[0][0]) + tid * 16;
            cp_async16(dst, gsrc);
        }
        cp_commit();
    }

    for (int t = tstart; t < tend; t++) {
        const int buf = (t - tstart) & 1;

        // fill(t) complete (per-thread), then barrier: cross-thread visibility
        // of fill(t) AND everyone done computing t-1 (safe to overwrite buf^1).
        cp_wait0();
        __syncthreads();

        // async-fill NEXT tile into the other buffer (overlaps compute below)
        if (t + 1 < tend) {
            int ndir, nb, nnbase, nms;
            decode_tile(t + 1, ndir, nb, nnbase, nms);
            if (tid < 256) {
                const float* gsrc = &g_prepB[ndir ^ 1][nb][(size_t)nms * JP * 8] + tid * 4;
                const uint32_t dst =
                    (uint32_t)__cvta_generic_to_shared(&tile[buf ^ 1][0]) + tid * 16;
                cp_async16(dst, gsrc);
            }
        }
        cp_commit();

        // A-chunk management for CURRENT tile
        const int ach = t >> 5;
        if (ach != cur_ach) {
            if (cur_ach >= 0) {          // flush previous A-chunk
                float* __restrict__ outd = cur_dir ? dist2 : dist1;
#pragma unroll
                for (int k = 0; k < PTS; k++) {
                    const int n = cur_nbase + k * THREADS + tid;
                    const float e = fminf(eminE[k], eminO[k]);
                    const float d = fmaxf(n1s[k] + e, 0.0f);
                    atomicMin((int*)&outd[(size_t)cur_b * Nc + n], __float_as_int(d));
                }
            }
            cur_ach = ach;
            int ms_un;
            decode_tile(t, cur_dir, cur_b, cur_nbase, ms_un);
            const float* __restrict__ P = cur_dir ? x2 : x1;
#pragma unroll
            for (int k = 0; k < PTS; k++) {
                const int n = cur_nbase + k * THREADS + tid;
                const float* p = P + ((size_t)cur_b * Nc + n) * 3;
                const float ax = p[0], ay = p[1], az = p[2];
                axp[k] = pk2(ax, ax);
                ayp[k] = pk2(ay, ay);
                azp[k] = pk2(az, az);
                n1s[k] = fmaf(ax, ax, fmaf(ay, ay, az * az));
                eminE[k] = CUDART_INF_F;
                eminO[k] = CUDART_INF_F;
            }
        }

        // compute CURRENT buffer
        const ulonglong2* sp = reinterpret_cast<const ulonglong2*>(tile[buf]);
#pragma unroll 8
        for (int jj = 0; jj < JP; jj++) {
            const ulonglong2 c0 = sp[2 * jj];       // {bx2_e,bx2_o} {by2_e,by2_o}
            const ulonglong2 c1 = sp[2 * jj + 1];   // {bz2_e,bz2_o} {n2_e,n2_o}
#pragma unroll
            for (int k = 0; k < PTS; k++) {
                unsigned long long e = ffma2(axp[k], c0.x, c1.y);
                e = ffma2(ayp[k], c0.y, e);
                e = ffma2(azp[k], c1.x, e);
                float flo, fhi;
                upk2(e, flo, fhi);
                eminE[k] = fminf(eminE[k], flo);
                eminO[k] = fminf(eminO[k], fhi);
            }
        }
    }

    if (cur_ach >= 0) {                  // final flush
        float* __restrict__ outd = cur_dir ? dist2 : dist1;
#pragma unroll
        for (int k = 0; k < PTS; k++) {
            const int n = cur_nbase + k * THREADS + tid;
            const float e = fminf(eminE[k], eminO[k]);
            const float d = fmaxf(n1s[k] + e, 0.0f);
            atomicMin((int*)&outd[(size_t)cur_b * Nc + n], __float_as_int(d));
        }
    }
}

// ---- deterministic 2-stage loss reduction ----
__global__ void __launch_bounds__(256)
sum_stage1(const float* __restrict__ dists)   // dists = out+1, length 2*B*N
{
    __shared__ float red[256];
    const int tid = threadIdx.x;
    const int base = blockIdx.x * 1024;
    float s = 0.0f;
#pragma unroll
    for (int i = 0; i < 4; i++) s += dists[base + i * 256 + tid];
    red[tid] = s;
    __syncthreads();
    for (int w = 128; w > 0; w >>= 1) {
        if (tid < w) red[tid] += red[tid + w];
        __syncthreads();
    }
    if (tid == 0) g_partials[blockIdx.x] = red[0];
}

__global__ void __launch_bounds__(128)
sum_stage2(float* __restrict__ out)
{
    __shared__ float red[128];
    const int tid = threadIdx.x;
    red[tid] = g_partials[tid];
    __syncthreads();
    for (int w = 64; w > 0; w >>= 1) {
        if (tid < w) red[tid] += red[tid + w];
        __syncthreads();
    }
    if (tid == 0) out[0] = red[0] * (1.0f / (float)(Bc * Nc));
}

extern "C" void kernel_launch(void* const* d_in, const int* in_sizes, int n_in,
                              void* d_out, int out_size)
{
    const float* x1 = (const float*)d_in[0];
    const float* x2 = (const float*)d_in[1];
    float* out = (float*)d_out;
    float* dist1 = out + 1;
    float* dist2 = out + 1 + Bc * Nc;

    // Sentinel-fill dist arrays: 0x7F7F7F7F = 3.39e38 > any real sq-distance.
    cudaMemsetAsync(out + 1, 0x7F, (size_t)2 * Bc * Nc * sizeof(float));

    prep_kernel<<<256, 256>>>(x1, x2);
    chamfer_pass_kernel<<<GRID, THREADS>>>(x1, x2, dist1, dist2);

    sum_stage1<<<128, 256>>>(out + 1);
    sum_stage2<<<1, 128>>>(out);
}